// round 1
// baseline (speedup 1.0000x reference)
#include <cuda_runtime.h>
#include <math.h>

#define BATCH 2
#define SEQ   2048
#define NH    8
#define HD    64
#define DM    512            // NH*HD
#define NROWS (BATCH*SEQ*NH) // 32768 rows of 64 for the QKV projections

// Scratch (static __device__ — no allocation anywhere)
__device__ float g_q[BATCH*SEQ*DM];
__device__ float g_k[BATCH*SEQ*DM];
__device__ float g_v[BATCH*SEQ*DM];
__device__ float g_ctx[BATCH*SEQ*DM];

// ---------------------------------------------------------------------------
// Swizzled 64x64 fp32 tile helpers.
// Logical element (row, col) lives at: row*64 + ((col>>2 ^ (row>>2)&7)<<2) + (col&3)
// => float4 reads down columns-of-rows are bank-conflict-free, as are the
//    float4 tile-fill stores.
// ---------------------------------------------------------------------------
__device__ __forceinline__ void load_tile_swz(float* __restrict__ dst,
                                              const float* __restrict__ src,
                                              int stride) {
    int t   = threadIdx.x;        // 256 threads
    int seg = t & 15;             // 16B segment within a 256B row
    int r   = t >> 4;             // 0..15
#pragma unroll
    for (int p = 0; p < 4; p++, r += 16) {
        float4 v = *(const float4*)(src + (size_t)r * stride + (seg << 2));
        int g = seg ^ ((r >> 2) & 7);
        *(float4*)(dst + r * 64 + (g << 2)) = v;
    }
}

// C[4][4] += A_tile · B_tile^T  (both tiles stored [row][inner], swizzled).
// Thread (ty,tx): rows ty*4+i of A, rows tx*4+j of B.
__device__ __forceinline__ void mm_acc(const float* __restrict__ As,
                                       const float* __restrict__ Bs,
                                       float c[4][4], int ty, int tx) {
#pragma unroll
    for (int d4 = 0; d4 < 16; d4++) {
        int oa = (ty * 4) * 64 + ((d4 ^ (ty & 7)) << 2);
        int ob = (tx * 4) * 64 + ((d4 ^ (tx & 7)) << 2);
        float4 a[4], b[4];
#pragma unroll
        for (int i = 0; i < 4; i++) a[i] = *(const float4*)(As + oa + i * 64);
#pragma unroll
        for (int j = 0; j < 4; j++) b[j] = *(const float4*)(Bs + ob + j * 64);
#pragma unroll
        for (int i = 0; i < 4; i++)
#pragma unroll
            for (int j = 0; j < 4; j++)
                c[i][j] += a[i].x * b[j].x + a[i].y * b[j].y +
                           a[i].z * b[j].z + a[i].w * b[j].w;
    }
}

// ---------------------------------------------------------------------------
// Kernel 1: per-head QKV projections. X[32768x64] @ W[64x64]^T + b
// grid (512, 3): y selects q/k/v.
// ---------------------------------------------------------------------------
__global__ void qkv_proj_kernel(const float* __restrict__ qin,
                                const float* __restrict__ kin,
                                const float* __restrict__ vin,
                                const float* __restrict__ Wq, const float* __restrict__ bq,
                                const float* __restrict__ Wk, const float* __restrict__ bk,
                                const float* __restrict__ Wv, const float* __restrict__ bv) {
    __shared__ float Xs[4096], Ws[4096];
    const float *in, *W, *bias;
    float* out;
    if (blockIdx.y == 0)      { in = qin; W = Wq; bias = bq; out = g_q; }
    else if (blockIdx.y == 1) { in = kin; W = Wk; bias = bk; out = g_k; }
    else                      { in = vin; W = Wv; bias = bv; out = g_v; }

    int r0 = blockIdx.x << 6;
    int t = threadIdx.x, tx = t & 15, ty = t >> 4;

    load_tile_swz(Xs, in + (size_t)r0 * 64, 64);
    load_tile_swz(Ws, W, 64);
    __syncthreads();

    float c[4][4] = {};
    mm_acc(Xs, Ws, c, ty, tx);

#pragma unroll
    for (int i = 0; i < 4; i++) {
        float4 o;
        o.x = c[i][0] + bias[tx * 4 + 0];
        o.y = c[i][1] + bias[tx * 4 + 1];
        o.z = c[i][2] + bias[tx * 4 + 2];
        o.w = c[i][3] + bias[tx * 4 + 3];
        *(float4*)(out + (size_t)(r0 + ty * 4 + i) * 64 + tx * 4) = o;
    }
}

// ---------------------------------------------------------------------------
// Kernel 2: flash attention, one (b,h,q-tile of 64) per block.
// Mask applied BEFORE the 0.25 scale (masked logit = -1e20*0.25 = -2.5e19,
// matching the reference exactly). Context written in (d*H + h) feature order.
// ---------------------------------------------------------------------------
__global__ void attn_kernel(const int* __restrict__ mask) {
    extern __shared__ float sm[];
    float* Qs = sm;
    float* Ks = sm + 4096;
    float* Vs = sm + 8192;
    float* Ps = sm + 12288;
    __shared__ int msk[64];

    int bh = blockIdx.y;
    int b = bh >> 3, h = bh & 7;
    int q0 = blockIdx.x << 6;
    int t = threadIdx.x, tx = t & 15, ty = t >> 4;

    load_tile_swz(Qs, g_q + ((size_t)(b * SEQ + q0) * NH + h) * HD, DM);

    float acc[4][4] = {};
    float m_run[4], l_run[4];
#pragma unroll
    for (int i = 0; i < 4; i++) { m_run[i] = -3.0e38f; l_run[i] = 0.f; }

    for (int kt = 0; kt < SEQ / 64; kt++) {
        int k0 = kt << 6;
        load_tile_swz(Ks, g_k + ((size_t)(b * SEQ + k0) * NH + h) * HD, DM);
        load_tile_swz(Vs, g_v + ((size_t)(b * SEQ + k0) * NH + h) * HD, DM);
        if (t < 64) msk[t] = mask[b * SEQ + k0 + t];
        __syncthreads();   // covers Qs on first iter too

        float s[4][4] = {};
        mm_acc(Qs, Ks, s, ty, tx);

        int mj[4];
#pragma unroll
        for (int j = 0; j < 4; j++) mj[j] = msk[tx * 4 + j];
#pragma unroll
        for (int i = 0; i < 4; i++)
#pragma unroll
            for (int j = 0; j < 4; j++)
                s[i][j] = mj[j] ? s[i][j] * 0.25f : -2.5e19f;

#pragma unroll
        for (int i = 0; i < 4; i++) {
            float mx = fmaxf(fmaxf(s[i][0], s[i][1]), fmaxf(s[i][2], s[i][3]));
            mx = fmaxf(mx, __shfl_xor_sync(0xffffffffu, mx, 1));
            mx = fmaxf(mx, __shfl_xor_sync(0xffffffffu, mx, 2));
            mx = fmaxf(mx, __shfl_xor_sync(0xffffffffu, mx, 4));
            mx = fmaxf(mx, __shfl_xor_sync(0xffffffffu, mx, 8));
            float m_new = fmaxf(m_run[i], mx);
            float alpha = __expf(m_run[i] - m_new);
            float rs = 0.f;
#pragma unroll
            for (int j = 0; j < 4; j++) {
                s[i][j] = __expf(s[i][j] - m_new);
                rs += s[i][j];
            }
            rs += __shfl_xor_sync(0xffffffffu, rs, 1);
            rs += __shfl_xor_sync(0xffffffffu, rs, 2);
            rs += __shfl_xor_sync(0xffffffffu, rs, 4);
            rs += __shfl_xor_sync(0xffffffffu, rs, 8);
            l_run[i] = l_run[i] * alpha + rs;
            m_run[i] = m_new;
#pragma unroll
            for (int j = 0; j < 4; j++) acc[i][j] *= alpha;
            // P tile (rows=q, cols=kv), swizzled float4 store (conflict-free)
            int off = (ty * 4 + i) * 64 + ((tx ^ (ty & 7)) << 2);
            *(float4*)(Ps + off) = make_float4(s[i][0], s[i][1], s[i][2], s[i][3]);
        }
        __syncthreads();

        // acc[i][d] += sum_v P[q][v] * V[v][d]
#pragma unroll
        for (int v4 = 0; v4 < 16; v4++) {
            int op = (ty * 4) * 64 + ((v4 ^ (ty & 7)) << 2);
            float4 p[4];
#pragma unroll
            for (int i = 0; i < 4; i++) p[i] = *(const float4*)(Ps + op + i * 64);
            int ov = (v4 * 4) * 64 + ((tx ^ (v4 & 7)) << 2);
            float4 v0 = *(const float4*)(Vs + ov);
            float4 v1 = *(const float4*)(Vs + ov + 64);
            float4 v2 = *(const float4*)(Vs + ov + 128);
            float4 v3 = *(const float4*)(Vs + ov + 192);
#pragma unroll
            for (int i = 0; i < 4; i++) {
                acc[i][0] += p[i].x * v0.x + p[i].y * v1.x + p[i].z * v2.x + p[i].w * v3.x;
                acc[i][1] += p[i].x * v0.y + p[i].y * v1.y + p[i].z * v2.y + p[i].w * v3.y;
                acc[i][2] += p[i].x * v0.z + p[i].y * v1.z + p[i].z * v2.z + p[i].w * v3.z;
                acc[i][3] += p[i].x * v0.w + p[i].y * v1.w + p[i].z * v2.w + p[i].w * v3.w;
            }
        }
        __syncthreads();
    }

    // context in (d*H + h) feature order (reference's bqdh flatten)
    float* outp = g_ctx + ((size_t)b * SEQ + q0) * DM;
#pragma unroll
    for (int i = 0; i < 4; i++) {
        float inv = 1.0f / l_run[i];
#pragma unroll
        for (int j = 0; j < 4; j++)
            outp[(ty * 4 + i) * DM + (tx * 4 + j) * NH + h] = acc[i][j] * inv;
    }
}

// ---------------------------------------------------------------------------
// Kernel 3: output projection. ctx[4096x512] @ Wo[512x512]^T + bo
// ---------------------------------------------------------------------------
__global__ void out_proj_kernel(const float* __restrict__ Wo,
                                const float* __restrict__ bo,
                                float* __restrict__ y) {
    __shared__ float Xs[4096], Ws[4096];
    int r0 = blockIdx.x << 6;
    int e0 = blockIdx.y << 6;
    int t = threadIdx.x, tx = t & 15, ty = t >> 4;

    float c[4][4] = {};
    for (int kt = 0; kt < DM / 64; kt++) {
        load_tile_swz(Xs, g_ctx + (size_t)r0 * DM + kt * 64, DM);
        load_tile_swz(Ws, Wo + (size_t)e0 * DM + kt * 64, DM);
        __syncthreads();
        mm_acc(Xs, Ws, c, ty, tx);
        __syncthreads();
    }

#pragma unroll
    for (int i = 0; i < 4; i++) {
        float4 o;
        o.x = c[i][0] + bo[e0 + tx * 4 + 0];
        o.y = c[i][1] + bo[e0 + tx * 4 + 1];
        o.z = c[i][2] + bo[e0 + tx * 4 + 2];
        o.w = c[i][3] + bo[e0 + tx * 4 + 3];
        *(float4*)(y + (size_t)(r0 + ty * 4 + i) * DM + e0 + tx * 4) = o;
    }
}

// ---------------------------------------------------------------------------
extern "C" void kernel_launch(void* const* d_in, const int* in_sizes, int n_in,
                              void* d_out, int out_size) {
    const float* query = (const float*)d_in[0];
    const float* key   = (const float*)d_in[1];
    const float* value = (const float*)d_in[2];
    const float* Wq    = (const float*)d_in[3];
    const float* bq    = (const float*)d_in[4];
    const float* Wk    = (const float*)d_in[5];
    const float* bk    = (const float*)d_in[6];
    const float* Wv    = (const float*)d_in[7];
    const float* bv    = (const float*)d_in[8];
    const float* Wo    = (const float*)d_in[9];
    const float* bo    = (const float*)d_in[10];
    const int*   mask  = (const int*)d_in[11];

    // 64KB dynamic smem for the attention kernel (idempotent host call;
    // not a stream op, safe under graph capture)
    cudaFuncSetAttribute(attn_kernel, cudaFuncAttributeMaxDynamicSharedMemorySize,
                         64 * 1024);

    qkv_proj_kernel<<<dim3(NROWS / 64, 3), 256>>>(query, key, value,
                                                  Wq, bq, Wk, bk, Wv, bv);
    attn_kernel<<<dim3(SEQ / 64, BATCH * NH), 256, 64 * 1024>>>(mask);
    out_proj_kernel<<<dim3(BATCH * SEQ / 64, DM / 64), 256>>>(Wo, bo, (float*)d_out);
}

// round 3
// speedup vs baseline: 1.7571x; 1.7571x over previous
#include <cuda_runtime.h>
#include <math.h>

#define BATCH 2
#define SEQ   2048
#define NH    8
#define HD    64
#define DM    512            // NH*HD
#define NROWS (BATCH*SEQ*NH) // 32768 rows of 64 for the QKV projections

typedef unsigned long long u64;

// Scratch (static __device__ — no allocation anywhere)
__device__ float g_q[BATCH*SEQ*DM];
__device__ float g_k[BATCH*SEQ*DM];
__device__ float g_v[BATCH*SEQ*DM];
__device__ float g_ctx[BATCH*SEQ*DM];
__device__ int   g_idx[BATCH*SEQ];   // compacted unmasked key indices per batch
__device__ int   g_cnt[BATCH];       // count of unmasked keys per batch

// ---------------------------------------------------------------------------
// Packed f32x2 helpers (sm_103a FFMA2): each u64 holds two fp32 lanes.
// ---------------------------------------------------------------------------
__device__ __forceinline__ void ffma2(u64 &c, u64 a, u64 b) {
    asm("fma.rn.f32x2 %0, %1, %2, %0;" : "+l"(c) : "l"(a), "l"(b));
}
__device__ __forceinline__ void fmul2(u64 &c, u64 a) {
    asm("mul.rn.f32x2 %0, %0, %1;" : "+l"(c) : "l"(a));
}
__device__ __forceinline__ u64 dup2(float x) {
    u64 r; asm("mov.b64 %0, {%1, %1};" : "=l"(r) : "f"(x)); return r;
}
__device__ __forceinline__ float plo(u64 c) { return __uint_as_float((unsigned)c); }
__device__ __forceinline__ float phi(u64 c) { return __uint_as_float((unsigned)(c >> 32)); }
__device__ __forceinline__ float psum(u64 c) { return plo(c) + phi(c); }

// ---------------------------------------------------------------------------
// Swizzled 64x64 fp32 tile helpers.
// (row, col) -> row*64 + ((col>>2 ^ (row>>2)&7)<<2) + (col&3)
// ---------------------------------------------------------------------------
__device__ __forceinline__ void load_tile_swz(float* __restrict__ dst,
                                              const float* __restrict__ src,
                                              int stride) {
    int t   = threadIdx.x;        // 256 threads
    int seg = t & 15;
    int r   = t >> 4;
#pragma unroll
    for (int p = 0; p < 4; p++, r += 16) {
        float4 v = *(const float4*)(src + (size_t)r * stride + (seg << 2));
        int g = seg ^ ((r >> 2) & 7);
        *(float4*)(dst + r * 64 + (g << 2)) = v;
    }
}

// Gathered variant: tile row r comes from source row idx[k0+r] (pad rows -> row 0).
__device__ __forceinline__ void load_tile_swz_gather(float* __restrict__ dst,
                                                     const float* __restrict__ base,
                                                     const int* __restrict__ idxb,
                                                     int k0, int cnt) {
    int t   = threadIdx.x;
    int seg = t & 15;
    int r   = t >> 4;
#pragma unroll
    for (int p = 0; p < 4; p++, r += 16) {
        int kr  = k0 + r;
        int row = (kr < cnt) ? idxb[kr] : 0;
        float4 v = *(const float4*)(base + (size_t)row * DM + (seg << 2));
        int g = seg ^ ((r >> 2) & 7);
        *(float4*)(dst + r * 64 + (g << 2)) = v;
    }
}

// C2[4][4] (packed over contraction d) += A_tile · B_tile^T.
// Both tiles [row][d], swizzled. Lane0 accumulates even-d, lane1 odd-d.
__device__ __forceinline__ void mm_acc_p(const float* __restrict__ As,
                                         const float* __restrict__ Bs,
                                         u64 c2[4][4], int ty, int tx) {
#pragma unroll
    for (int d4 = 0; d4 < 16; d4++) {
        int oa = (ty * 4) * 64 + ((d4 ^ (ty & 7)) << 2);
        int ob = (tx * 4) * 64 + ((d4 ^ (tx & 7)) << 2);
        ulonglong2 a[4], b[4];
#pragma unroll
        for (int i = 0; i < 4; i++) a[i] = *(const ulonglong2*)(As + oa + i * 64);
#pragma unroll
        for (int j = 0; j < 4; j++) b[j] = *(const ulonglong2*)(Bs + ob + j * 64);
#pragma unroll
        for (int i = 0; i < 4; i++)
#pragma unroll
            for (int j = 0; j < 4; j++) {
                ffma2(c2[i][j], a[i].x, b[j].x);
                ffma2(c2[i][j], a[i].y, b[j].y);
            }
    }
}

// ---------------------------------------------------------------------------
// Kernel 0: per-batch mask compaction (exact: masked keys softmax to 0.0f).
// ---------------------------------------------------------------------------
__global__ void compact_kernel(const int* __restrict__ mask) {
    __shared__ int cnts[256];
    int b = blockIdx.x;
    int t = threadIdx.x;
    int m[8], c = 0;
#pragma unroll
    for (int e = 0; e < 8; e++) {
        m[e] = mask[b * SEQ + t * 8 + e];
        c += (m[e] != 0);
    }
    cnts[t] = c;
    __syncthreads();
    // inclusive scan over 256 per-thread counts
    for (int off = 1; off < 256; off <<= 1) {
        int u = (t >= off) ? cnts[t - off] : 0;
        __syncthreads();
        cnts[t] += u;
        __syncthreads();
    }
    int w = cnts[t] - c;  // exclusive prefix
#pragma unroll
    for (int e = 0; e < 8; e++)
        if (m[e]) g_idx[b * SEQ + (w++)] = t * 8 + e;
    if (t == 255) g_cnt[b] = cnts[255];
}

// ---------------------------------------------------------------------------
// Kernel 1: per-head QKV projections. X[32768x64] @ W[64x64]^T + b
// ---------------------------------------------------------------------------
__global__ void qkv_proj_kernel(const float* __restrict__ qin,
                                const float* __restrict__ kin,
                                const float* __restrict__ vin,
                                const float* __restrict__ Wq, const float* __restrict__ bq,
                                const float* __restrict__ Wk, const float* __restrict__ bk,
                                const float* __restrict__ Wv, const float* __restrict__ bv) {
    __shared__ float Xs[4096], Ws[4096];
    const float *in, *W, *bias;
    float* out;
    if (blockIdx.y == 0)      { in = qin; W = Wq; bias = bq; out = g_q; }
    else if (blockIdx.y == 1) { in = kin; W = Wk; bias = bk; out = g_k; }
    else                      { in = vin; W = Wv; bias = bv; out = g_v; }

    int r0 = blockIdx.x << 6;
    int t = threadIdx.x, tx = t & 15, ty = t >> 4;

    load_tile_swz(Xs, in + (size_t)r0 * 64, 64);
    load_tile_swz(Ws, W, 64);
    __syncthreads();

    u64 c2[4][4] = {};
    mm_acc_p(Xs, Ws, c2, ty, tx);

#pragma unroll
    for (int i = 0; i < 4; i++) {
        float4 o;
        o.x = psum(c2[i][0]) + bias[tx * 4 + 0];
        o.y = psum(c2[i][1]) + bias[tx * 4 + 1];
        o.z = psum(c2[i][2]) + bias[tx * 4 + 2];
        o.w = psum(c2[i][3]) + bias[tx * 4 + 3];
        *(float4*)(out + (size_t)(r0 + ty * 4 + i) * 64 + tx * 4) = o;
    }
}

// ---------------------------------------------------------------------------
// Kernel 2: flash attention over COMPACTED keys.
// ---------------------------------------------------------------------------
__global__ void attn_kernel() {
    extern __shared__ float sm[];
    float* Qs = sm;
    float* Ks = sm + 4096;
    float* Vs = sm + 8192;
    float* Ps = sm + 12288;

    int bh = blockIdx.y;
    int b = bh >> 3, h = bh & 7;
    int q0 = blockIdx.x << 6;
    int t = threadIdx.x, tx = t & 15, ty = t >> 4;

    int cnt = g_cnt[b];
    const int* idxb = g_idx + b * SEQ;
    const float* kbase = g_k + ((size_t)(b * SEQ) * NH + h) * HD;
    const float* vbase = g_v + ((size_t)(b * SEQ) * NH + h) * HD;

    load_tile_swz(Qs, g_q + ((size_t)(b * SEQ + q0) * NH + h) * HD, DM);

    // PV accumulators packed over OUTPUT d pairs: acc2[i][j2] lanes=(d=2j2, d=2j2+1)
    u64 acc2[4][2] = {};
    float m_run[4], l_run[4];
#pragma unroll
    for (int i = 0; i < 4; i++) { m_run[i] = -3.0e38f; l_run[i] = 0.f; }

    int nkt = (cnt + 63) >> 6;
    for (int kt = 0; kt < nkt; kt++) {
        int k0 = kt << 6;
        load_tile_swz_gather(Ks, kbase, idxb, k0, cnt);
        load_tile_swz_gather(Vs, vbase, idxb, k0, cnt);
        __syncthreads();   // covers Qs on first iter too

        u64 s2[4][4] = {};
        mm_acc_p(Qs, Ks, s2, ty, tx);

        float s[4][4];
#pragma unroll
        for (int i = 0; i < 4; i++)
#pragma unroll
            for (int j = 0; j < 4; j++) {
                bool valid = (k0 + tx * 4 + j) < cnt;
                s[i][j] = valid ? psum(s2[i][j]) * 0.25f : -3.0e38f;
            }

#pragma unroll
        for (int i = 0; i < 4; i++) {
            float mx = fmaxf(fmaxf(s[i][0], s[i][1]), fmaxf(s[i][2], s[i][3]));
            mx = fmaxf(mx, __shfl_xor_sync(0xffffffffu, mx, 1));
            mx = fmaxf(mx, __shfl_xor_sync(0xffffffffu, mx, 2));
            mx = fmaxf(mx, __shfl_xor_sync(0xffffffffu, mx, 4));
            mx = fmaxf(mx, __shfl_xor_sync(0xffffffffu, mx, 8));
            float m_new = fmaxf(m_run[i], mx);
            float alpha = __expf(m_run[i] - m_new);
            float rs = 0.f;
#pragma unroll
            for (int j = 0; j < 4; j++) {
                s[i][j] = __expf(s[i][j] - m_new);
                rs += s[i][j];
            }
            rs += __shfl_xor_sync(0xffffffffu, rs, 1);
            rs += __shfl_xor_sync(0xffffffffu, rs, 2);
            rs += __shfl_xor_sync(0xffffffffu, rs, 4);
            rs += __shfl_xor_sync(0xffffffffu, rs, 8);
            l_run[i] = l_run[i] * alpha + rs;
            m_run[i] = m_new;
            u64 al = dup2(alpha);
            fmul2(acc2[i][0], al);
            fmul2(acc2[i][1], al);
            int off = (ty * 4 + i) * 64 + ((tx ^ (ty & 7)) << 2);
            *(float4*)(Ps + off) = make_float4(s[i][0], s[i][1], s[i][2], s[i][3]);
        }
        __syncthreads();

        // acc2[i][:] += sum_v P[q][v] * V[v][:]  (dup'd P scalar × packed V row)
#pragma unroll
        for (int v4 = 0; v4 < 16; v4++) {
            int op = (ty * 4) * 64 + ((v4 ^ (ty & 7)) << 2);
            float4 p[4];
#pragma unroll
            for (int i = 0; i < 4; i++) p[i] = *(const float4*)(Ps + op + i * 64);
            int ov = (v4 * 4) * 64 + ((tx ^ (v4 & 7)) << 2);
            ulonglong2 vr[4];
#pragma unroll
            for (int vv = 0; vv < 4; vv++)
                vr[vv] = *(const ulonglong2*)(Vs + ov + vv * 64);
#pragma unroll
            for (int i = 0; i < 4; i++) {
                u64 p0 = dup2(p[i].x), p1 = dup2(p[i].y);
                u64 p2 = dup2(p[i].z), p3 = dup2(p[i].w);
                ffma2(acc2[i][0], p0, vr[0].x); ffma2(acc2[i][1], p0, vr[0].y);
                ffma2(acc2[i][0], p1, vr[1].x); ffma2(acc2[i][1], p1, vr[1].y);
                ffma2(acc2[i][0], p2, vr[2].x); ffma2(acc2[i][1], p2, vr[2].y);
                ffma2(acc2[i][0], p3, vr[3].x); ffma2(acc2[i][1], p3, vr[3].y);
            }
        }
        __syncthreads();
    }

    // context in (d*H + h) feature order
    float* outp = g_ctx + ((size_t)b * SEQ + q0) * DM;
#pragma unroll
    for (int i = 0; i < 4; i++) {
        float inv = 1.0f / l_run[i];
        float d0 = plo(acc2[i][0]) * inv, d1 = phi(acc2[i][0]) * inv;
        float d2 = plo(acc2[i][1]) * inv, d3 = phi(acc2[i][1]) * inv;
        float* row = outp + (size_t)(ty * 4 + i) * DM + h;
        row[(tx * 4 + 0) * NH] = d0;
        row[(tx * 4 + 1) * NH] = d1;
        row[(tx * 4 + 2) * NH] = d2;
        row[(tx * 4 + 3) * NH] = d3;
    }
}

// ---------------------------------------------------------------------------
// Kernel 3: output projection. ctx[4096x512] @ Wo[512x512]^T + bo
// ---------------------------------------------------------------------------
__global__ void out_proj_kernel(const float* __restrict__ Wo,
                                const float* __restrict__ bo,
                                float* __restrict__ y) {
    __shared__ float Xs[4096], Ws[4096];
    int r0 = blockIdx.x << 6;
    int e0 = blockIdx.y << 6;
    int t = threadIdx.x, tx = t & 15, ty = t >> 4;

    u64 c2[4][4] = {};
    for (int kt = 0; kt < DM / 64; kt++) {
        load_tile_swz(Xs, g_ctx + (size_t)r0 * DM + kt * 64, DM);
        load_tile_swz(Ws, Wo + (size_t)e0 * DM + kt * 64, DM);
        __syncthreads();
        mm_acc_p(Xs, Ws, c2, ty, tx);
        __syncthreads();
    }

#pragma unroll
    for (int i = 0; i < 4; i++) {
        float4 o;
        o.x = psum(c2[i][0]) + bo[e0 + tx * 4 + 0];
        o.y = psum(c2[i][1]) + bo[e0 + tx * 4 + 1];
        o.z = psum(c2[i][2]) + bo[e0 + tx * 4 + 2];
        o.w = psum(c2[i][3]) + bo[e0 + tx * 4 + 3];
        *(float4*)(y + (size_t)(r0 + ty * 4 + i) * DM + e0 + tx * 4) = o;
    }
}

// ---------------------------------------------------------------------------
extern "C" void kernel_launch(void* const* d_in, const int* in_sizes, int n_in,
                              void* d_out, int out_size) {
    const float* query = (const float*)d_in[0];
    const float* key   = (const float*)d_in[1];
    const float* value = (const float*)d_in[2];
    const float* Wq    = (const float*)d_in[3];
    const float* bq    = (const float*)d_in[4];
    const float* Wk    = (const float*)d_in[5];
    const float* bk    = (const float*)d_in[6];
    const float* Wv    = (const float*)d_in[7];
    const float* bv    = (const float*)d_in[8];
    const float* Wo    = (const float*)d_in[9];
    const float* bo    = (const float*)d_in[10];
    const int*   mask  = (const int*)d_in[11];

    cudaFuncSetAttribute(attn_kernel, cudaFuncAttributeMaxDynamicSharedMemorySize,
                         64 * 1024);

    compact_kernel<<<BATCH, 256>>>(mask);
    qkv_proj_kernel<<<dim3(NROWS / 64, 3), 256>>>(query, key, value,
                                                  Wq, bq, Wk, bk, Wv, bv);
    attn_kernel<<<dim3(SEQ / 64, BATCH * NH), 256, 64 * 1024>>>();
    out_proj_kernel<<<dim3(BATCH * SEQ / 64, DM / 64), 256>>>(Wo, bo, (float*)d_out);
}

// round 4
// speedup vs baseline: 3.4450x; 1.9606x over previous
#include <cuda_runtime.h>
#include <cuda_bf16.h>
#include <math.h>
#include <stdint.h>

#define BATCH 2
#define SEQ   2048
#define NH    8
#define HD    64
#define DM    512
#define NROWS (BATCH*SEQ*NH)

typedef unsigned long long u64;
typedef unsigned int u32;

// Scratch (static __device__ — no allocation anywhere)
__device__ float g_ctx[BATCH*SEQ*DM];
__device__ __nv_bfloat16 g_qh[(size_t)NROWS*HD], g_ql[(size_t)NROWS*HD];
__device__ __nv_bfloat16 g_kh[(size_t)NROWS*HD], g_kl[(size_t)NROWS*HD];
__device__ __nv_bfloat16 g_vh[(size_t)NROWS*HD], g_vl[(size_t)NROWS*HD];
__device__ int g_idx[BATCH*SEQ];
__device__ int g_cnt[BATCH];

// ---------------------------------------------------------------------------
// Packed f32x2 helpers (kept for the fp32 projection kernels)
// ---------------------------------------------------------------------------
__device__ __forceinline__ void ffma2(u64 &c, u64 a, u64 b) {
    asm("fma.rn.f32x2 %0, %1, %2, %0;" : "+l"(c) : "l"(a), "l"(b));
}
__device__ __forceinline__ float plo(u64 c) { return __uint_as_float((unsigned)c); }
__device__ __forceinline__ float phi(u64 c) { return __uint_as_float((unsigned)(c >> 32)); }
__device__ __forceinline__ float psum(u64 c) { return plo(c) + phi(c); }

// ---------------------------------------------------------------------------
// fp32 64x64 swizzled tile helpers (projection kernels)
// ---------------------------------------------------------------------------
__device__ __forceinline__ void load_tile_swz(float* __restrict__ dst,
                                              const float* __restrict__ src,
                                              int stride) {
    int t   = threadIdx.x;        // 256 threads
    int seg = t & 15;
    int r   = t >> 4;
#pragma unroll
    for (int p = 0; p < 4; p++, r += 16) {
        float4 v = *(const float4*)(src + (size_t)r * stride + (seg << 2));
        int g = seg ^ ((r >> 2) & 7);
        *(float4*)(dst + r * 64 + (g << 2)) = v;
    }
}

__device__ __forceinline__ void mm_acc_p(const float* __restrict__ As,
                                         const float* __restrict__ Bs,
                                         u64 c2[4][4], int ty, int tx) {
#pragma unroll
    for (int d4 = 0; d4 < 16; d4++) {
        int oa = (ty * 4) * 64 + ((d4 ^ (ty & 7)) << 2);
        int ob = (tx * 4) * 64 + ((d4 ^ (tx & 7)) << 2);
        ulonglong2 a[4], b[4];
#pragma unroll
        for (int i = 0; i < 4; i++) a[i] = *(const ulonglong2*)(As + oa + i * 64);
#pragma unroll
        for (int j = 0; j < 4; j++) b[j] = *(const ulonglong2*)(Bs + ob + j * 64);
#pragma unroll
        for (int i = 0; i < 4; i++)
#pragma unroll
            for (int j = 0; j < 4; j++) {
                ffma2(c2[i][j], a[i].x, b[j].x);
                ffma2(c2[i][j], a[i].y, b[j].y);
            }
    }
}

// ---------------------------------------------------------------------------
// HMMA helpers
// ---------------------------------------------------------------------------
__device__ __forceinline__ u32 s2u(const void* p) {
    return (u32)__cvta_generic_to_shared(p);
}
__device__ __forceinline__ void ldsm4(u32 &r0, u32 &r1, u32 &r2, u32 &r3, u32 a) {
    asm volatile("ldmatrix.sync.aligned.m8n8.x4.shared.b16 {%0,%1,%2,%3}, [%4];"
                 : "=r"(r0), "=r"(r1), "=r"(r2), "=r"(r3) : "r"(a));
}
__device__ __forceinline__ void ldsm2(u32 &r0, u32 &r1, u32 a) {
    asm volatile("ldmatrix.sync.aligned.m8n8.x2.shared.b16 {%0,%1}, [%2];"
                 : "=r"(r0), "=r"(r1) : "r"(a));
}
__device__ __forceinline__ void ldsm2t(u32 &r0, u32 &r1, u32 a) {
    asm volatile("ldmatrix.sync.aligned.m8n8.x2.trans.shared.b16 {%0,%1}, [%2];"
                 : "=r"(r0), "=r"(r1) : "r"(a));
}
__device__ __forceinline__ void mmabf(float c[4], const u32 a[4], u32 b0, u32 b1) {
    asm volatile("mma.sync.aligned.m16n8k16.row.col.f32.bf16.bf16.f32 "
                 "{%0,%1,%2,%3}, {%4,%5,%6,%7}, {%8,%9}, {%0,%1,%2,%3};"
                 : "+f"(c[0]), "+f"(c[1]), "+f"(c[2]), "+f"(c[3])
                 : "r"(a[0]), "r"(a[1]), "r"(a[2]), "r"(a[3]), "r"(b0), "r"(b1));
}
// split (f0,f1) -> packed bf16 hi and lo pairs (f0 in lower half)
__device__ __forceinline__ void split_pair(float f0, float f1, u32 &hi, u32 &lo) {
    __nv_bfloat162 h = __floats2bfloat162_rn(f0, f1);
    float hf0 = __bfloat162float(h.x), hf1 = __bfloat162float(h.y);
    __nv_bfloat162 l = __floats2bfloat162_rn(f0 - hf0, f1 - hf1);
    hi = *reinterpret_cast<u32*>(&h);
    lo = *reinterpret_cast<u32*>(&l);
}

// ---------------------------------------------------------------------------
// bf16 tile fills (swizzled 128B rows: physical seg = seg ^ (row&7))
// ---------------------------------------------------------------------------
__device__ __forceinline__ void fill_bf16_gather(__nv_bfloat16* __restrict__ dst,
                                                 const __nv_bfloat16* __restrict__ base,
                                                 const int* __restrict__ idxb,
                                                 int k0, int cnt, int t) {
    int seg = t & 7;
    int r   = t >> 3;          // 16 rows per pass, 128 threads
#pragma unroll
    for (int p = 0; p < 4; p++, r += 16) {
        int kr  = k0 + r;
        int row = (kr < cnt) ? idxb[kr] : 0;
        uint4 v = *((const uint4*)(base + (size_t)row * DM) + seg);
        *((uint4*)(dst + r * HD + ((seg ^ (r & 7)) << 3))) = v;
    }
}
__device__ __forceinline__ void fill_bf16_str(__nv_bfloat16* __restrict__ dst,
                                              const __nv_bfloat16* __restrict__ base,
                                              int t) {
    int seg = t & 7;
    int r   = t >> 3;
#pragma unroll
    for (int p = 0; p < 4; p++, r += 16) {
        uint4 v = *((const uint4*)(base + (size_t)r * DM) + seg);
        *((uint4*)(dst + r * HD + ((seg ^ (r & 7)) << 3))) = v;
    }
}

// ---------------------------------------------------------------------------
// Kernel 0: per-batch mask compaction (exact: masked keys softmax to 0.0f).
// ---------------------------------------------------------------------------
__global__ void compact_kernel(const int* __restrict__ mask) {
    __shared__ int cnts[256];
    int b = blockIdx.x;
    int t = threadIdx.x;
    int m[8], c = 0;
#pragma unroll
    for (int e = 0; e < 8; e++) {
        m[e] = mask[b * SEQ + t * 8 + e];
        c += (m[e] != 0);
    }
    cnts[t] = c;
    __syncthreads();
    for (int off = 1; off < 256; off <<= 1) {
        int u = (t >= off) ? cnts[t - off] : 0;
        __syncthreads();
        cnts[t] += u;
        __syncthreads();
    }
    int w = cnts[t] - c;
#pragma unroll
    for (int e = 0; e < 8; e++)
        if (m[e]) g_idx[b * SEQ + (w++)] = t * 8 + e;
    if (t == 255) g_cnt[b] = cnts[255];
}

// ---------------------------------------------------------------------------
// Kernel 1: per-head QKV projections -> bf16 hi/lo outputs.
// ---------------------------------------------------------------------------
__global__ void qkv_proj_kernel(const float* __restrict__ qin,
                                const float* __restrict__ kin,
                                const float* __restrict__ vin,
                                const float* __restrict__ Wq, const float* __restrict__ bq,
                                const float* __restrict__ Wk, const float* __restrict__ bk,
                                const float* __restrict__ Wv, const float* __restrict__ bv) {
    __shared__ float Xs[4096], Ws[4096];
    const float *in, *W, *bias;
    __nv_bfloat16 *outh, *outl;
    if (blockIdx.y == 0)      { in = qin; W = Wq; bias = bq; outh = g_qh; outl = g_ql; }
    else if (blockIdx.y == 1) { in = kin; W = Wk; bias = bk; outh = g_kh; outl = g_kl; }
    else                      { in = vin; W = Wv; bias = bv; outh = g_vh; outl = g_vl; }

    int r0 = blockIdx.x << 6;
    int t = threadIdx.x, tx = t & 15, ty = t >> 4;

    load_tile_swz(Xs, in + (size_t)r0 * 64, 64);
    load_tile_swz(Ws, W, 64);
    __syncthreads();

    u64 c2[4][4] = {};
    mm_acc_p(Xs, Ws, c2, ty, tx);

#pragma unroll
    for (int i = 0; i < 4; i++) {
        float v0 = psum(c2[i][0]) + bias[tx * 4 + 0];
        float v1 = psum(c2[i][1]) + bias[tx * 4 + 1];
        float v2 = psum(c2[i][2]) + bias[tx * 4 + 2];
        float v3 = psum(c2[i][3]) + bias[tx * 4 + 3];
        u32 h01, l01, h23, l23;
        split_pair(v0, v1, h01, l01);
        split_pair(v2, v3, h23, l23);
        size_t o = (size_t)(r0 + ty * 4 + i) * 64 + tx * 4;
        *(uint2*)(outh + o) = make_uint2(h01, h23);
        *(uint2*)(outl + o) = make_uint2(l01, l23);
    }
}

// ---------------------------------------------------------------------------
// Kernel 2: HMMA flash attention over COMPACTED keys (bf16 hi/lo split).
// 128 threads = 4 warps; warp w owns q-rows [16w, 16w+16).
// ---------------------------------------------------------------------------
__global__ void __launch_bounds__(128) attn_kernel() {
    extern __shared__ __nv_bfloat16 sm[];
    __nv_bfloat16* Kh = sm;
    __nv_bfloat16* Kl = sm + 4096;
    __nv_bfloat16* Vh = sm + 8192;
    __nv_bfloat16* Vl = sm + 12288;

    int bh = blockIdx.y;
    int b = bh >> 3, h = bh & 7;
    int q0 = blockIdx.x << 6;
    int t = threadIdx.x, w = t >> 5, lane = t & 31;

    int cnt = g_cnt[b];
    const int* idxb = g_idx + b * SEQ;

    const __nv_bfloat16* qhb = g_qh + ((size_t)(b * SEQ + q0) * NH + h) * HD;
    const __nv_bfloat16* qlb = g_ql + ((size_t)(b * SEQ + q0) * NH + h) * HD;
    const __nv_bfloat16* khb = g_kh + ((size_t)b * SEQ * NH + h) * HD;
    const __nv_bfloat16* klb = g_kl + ((size_t)b * SEQ * NH + h) * HD;
    const __nv_bfloat16* vhb = g_vh + ((size_t)b * SEQ * NH + h) * HD;
    const __nv_bfloat16* vlb = g_vl + ((size_t)b * SEQ * NH + h) * HD;

    // ---- stage Q (reuse Kh/Kl smem), load A fragments ----
    fill_bf16_str(Kh, qhb, t);
    fill_bf16_str(Kl, qlb, t);
    __syncthreads();

    u32 qh[4][4], ql[4][4];
    {
        int r = (w << 4) + (lane & 7) + (((lane >> 3) & 1) << 3);
#pragma unroll
        for (int ks = 0; ks < 4; ks++) {
            int seg = (ks << 1) + (lane >> 4);
            u32 off = (u32)(r * HD + ((seg ^ (r & 7)) << 3)) * 2;
            ldsm4(qh[ks][0], qh[ks][1], qh[ks][2], qh[ks][3], s2u(Kh) + off);
            ldsm4(ql[ks][0], ql[ks][1], ql[ks][2], ql[ks][3], s2u(Kl) + off);
        }
    }
    __syncthreads();

    float out[8][4] = {};
    float m0 = -3.0e38f, m1 = -3.0e38f, l0 = 0.f, l1 = 0.f;

    int nkt = (cnt + 63) >> 6;
    for (int kt = 0; kt < nkt; kt++) {
        int k0 = kt << 6;
        fill_bf16_gather(Kh, khb, idxb, k0, cnt, t);
        fill_bf16_gather(Kl, klb, idxb, k0, cnt, t);
        fill_bf16_gather(Vh, vhb, idxb, k0, cnt, t);
        fill_bf16_gather(Vl, vlb, idxb, k0, cnt, t);
        __syncthreads();

        // ---- S = Q · K^T (split: hi*hi + hi*lo + lo*hi) ----
        float sacc[8][4] = {};
#pragma unroll
        for (int nb = 0; nb < 8; nb++) {
            int brow = (nb << 3) + (lane & 7);
#pragma unroll
            for (int ks = 0; ks < 4; ks++) {
                int seg = (ks << 1) + ((lane >> 3) & 1);
                u32 off = (u32)(brow * HD + ((seg ^ (brow & 7)) << 3)) * 2;
                u32 bh0, bh1, bl0, bl1;
                ldsm2(bh0, bh1, s2u(Kh) + off);
                ldsm2(bl0, bl1, s2u(Kl) + off);
                mmabf(sacc[nb], qh[ks], bh0, bh1);
                mmabf(sacc[nb], qh[ks], bl0, bl1);
                mmabf(sacc[nb], ql[ks], bh0, bh1);
            }
        }

        // ---- masked-scale + online softmax (2 q-rows per thread) ----
        float mx0 = -3.0e38f, mx1 = -3.0e38f;
#pragma unroll
        for (int nb = 0; nb < 8; nb++)
#pragma unroll
            for (int jj = 0; jj < 2; jj++) {
                int col = k0 + (nb << 3) + ((lane & 3) << 1) + jj;
                bool ok = col < cnt;
                float x0 = ok ? sacc[nb][jj]     * 0.25f : -3.0e38f;
                float x1 = ok ? sacc[nb][2 + jj] * 0.25f : -3.0e38f;
                sacc[nb][jj] = x0;  sacc[nb][2 + jj] = x1;
                mx0 = fmaxf(mx0, x0);  mx1 = fmaxf(mx1, x1);
            }
        mx0 = fmaxf(mx0, __shfl_xor_sync(0xffffffffu, mx0, 1));
        mx0 = fmaxf(mx0, __shfl_xor_sync(0xffffffffu, mx0, 2));
        mx1 = fmaxf(mx1, __shfl_xor_sync(0xffffffffu, mx1, 1));
        mx1 = fmaxf(mx1, __shfl_xor_sync(0xffffffffu, mx1, 2));
        float mn0 = fmaxf(m0, mx0), mn1 = fmaxf(m1, mx1);
        float a0 = __expf(m0 - mn0), a1 = __expf(m1 - mn1);
        float rs0 = 0.f, rs1 = 0.f;
#pragma unroll
        for (int nb = 0; nb < 8; nb++)
#pragma unroll
            for (int jj = 0; jj < 2; jj++) {
                float p0 = __expf(sacc[nb][jj]     - mn0);
                float p1 = __expf(sacc[nb][2 + jj] - mn1);
                sacc[nb][jj] = p0;  sacc[nb][2 + jj] = p1;
                rs0 += p0;  rs1 += p1;
            }
        rs0 += __shfl_xor_sync(0xffffffffu, rs0, 1);
        rs0 += __shfl_xor_sync(0xffffffffu, rs0, 2);
        rs1 += __shfl_xor_sync(0xffffffffu, rs1, 1);
        rs1 += __shfl_xor_sync(0xffffffffu, rs1, 2);
        l0 = l0 * a0 + rs0;  l1 = l1 * a1 + rs1;
        m0 = mn0;  m1 = mn1;
#pragma unroll
        for (int nbd = 0; nbd < 8; nbd++) {
            out[nbd][0] *= a0;  out[nbd][1] *= a0;
            out[nbd][2] *= a1;  out[nbd][3] *= a1;
        }

        // ---- repack P (C-frag) into A-frags, bf16 hi/lo ----
        u32 ph[4][4], pl[4][4];
#pragma unroll
        for (int e = 0; e < 4; e++) {
            int n0 = 2 * e, n1 = 2 * e + 1;
            split_pair(sacc[n0][0], sacc[n0][1], ph[e][0], pl[e][0]);
            split_pair(sacc[n0][2], sacc[n0][3], ph[e][1], pl[e][1]);
            split_pair(sacc[n1][0], sacc[n1][1], ph[e][2], pl[e][2]);
            split_pair(sacc[n1][2], sacc[n1][3], ph[e][3], pl[e][3]);
        }

        // ---- O += P · V (V^T via ldmatrix.trans; split products) ----
#pragma unroll
        for (int nbd = 0; nbd < 8; nbd++) {
#pragma unroll
            for (int e = 0; e < 4; e++) {
                int vrow = (e << 4) + (lane & 15);
                u32 off = (u32)(vrow * HD + ((nbd ^ (vrow & 7)) << 3)) * 2;
                u32 vh0, vh1, vl0, vl1;
                ldsm2t(vh0, vh1, s2u(Vh) + off);
                ldsm2t(vl0, vl1, s2u(Vl) + off);
                mmabf(out[nbd], ph[e], vh0, vh1);
                mmabf(out[nbd], ph[e], vl0, vl1);
                mmabf(out[nbd], pl[e], vh0, vh1);
            }
        }
        __syncthreads();
    }

    // ---- epilogue: ctx in (d*NH + h) feature order ----
    float inv0 = 1.0f / l0, inv1 = 1.0f / l1;
    int row0 = q0 + (w << 4) + (lane >> 2);
    float* o0 = g_ctx + ((size_t)b * SEQ + row0) * DM + h;
    float* o1 = o0 + 8 * DM;
#pragma unroll
    for (int nbd = 0; nbd < 8; nbd++)
#pragma unroll
        for (int jj = 0; jj < 2; jj++) {
            int d = (nbd << 3) + ((lane & 3) << 1) + jj;
            o0[d * NH] = out[nbd][jj]     * inv0;
            o1[d * NH] = out[nbd][2 + jj] * inv1;
        }
}

// ---------------------------------------------------------------------------
// Kernel 3: output projection. ctx[4096x512] @ Wo[512x512]^T + bo
// ---------------------------------------------------------------------------
__global__ void out_proj_kernel(const float* __restrict__ Wo,
                                const float* __restrict__ bo,
                                float* __restrict__ y) {
    __shared__ float Xs[4096], Ws[4096];
    int r0 = blockIdx.x << 6;
    int e0 = blockIdx.y << 6;
    int t = threadIdx.x, tx = t & 15, ty = t >> 4;

    u64 c2[4][4] = {};
    for (int kt = 0; kt < DM / 64; kt++) {
        load_tile_swz(Xs, g_ctx + (size_t)r0 * DM + kt * 64, DM);
        load_tile_swz(Ws, Wo + (size_t)e0 * DM + kt * 64, DM);
        __syncthreads();
        mm_acc_p(Xs, Ws, c2, ty, tx);
        __syncthreads();
    }

#pragma unroll
    for (int i = 0; i < 4; i++) {
        float4 o;
        o.x = psum(c2[i][0]) + bo[e0 + tx * 4 + 0];
        o.y = psum(c2[i][1]) + bo[e0 + tx * 4 + 1];
        o.z = psum(c2[i][2]) + bo[e0 + tx * 4 + 2];
        o.w = psum(c2[i][3]) + bo[e0 + tx * 4 + 3];
        *(float4*)(y + (size_t)(r0 + ty * 4 + i) * DM + e0 + tx * 4) = o;
    }
}

// ---------------------------------------------------------------------------
extern "C" void kernel_launch(void* const* d_in, const int* in_sizes, int n_in,
                              void* d_out, int out_size) {
    const float* query = (const float*)d_in[0];
    const float* key   = (const float*)d_in[1];
    const float* value = (const float*)d_in[2];
    const float* Wq    = (const float*)d_in[3];
    const float* bq    = (const float*)d_in[4];
    const float* Wk    = (const float*)d_in[5];
    const float* bk    = (const float*)d_in[6];
    const float* Wv    = (const float*)d_in[7];
    const float* bv    = (const float*)d_in[8];
    const float* Wo    = (const float*)d_in[9];
    const float* bo    = (const float*)d_in[10];
    const int*   mask  = (const int*)d_in[11];

    cudaFuncSetAttribute(attn_kernel, cudaFuncAttributeMaxDynamicSharedMemorySize,
                         48 * 1024);

    compact_kernel<<<BATCH, 256>>>(mask);
    qkv_proj_kernel<<<dim3(NROWS / 64, 3), 256>>>(query, key, value,
                                                  Wq, bq, Wk, bk, Wv, bv);
    attn_kernel<<<dim3(SEQ / 64, BATCH * NH), 128, 32 * 1024>>>();
    out_proj_kernel<<<dim3(BATCH * SEQ / 64, DM / 64), 256>>>(Wo, bo, (float*)d_out);
}

// round 6
// speedup vs baseline: 4.1789x; 1.2130x over previous
#include <cuda_runtime.h>
#include <cuda_bf16.h>
#include <math.h>
#include <stdint.h>

#define BATCH 2
#define SEQ   2048
#define NH    8
#define HD    64
#define DM    512
#define NROWS (BATCH*SEQ*NH)

typedef unsigned long long u64;
typedef unsigned int u32;

// Scratch (static __device__ — no allocation anywhere)
__device__ __nv_bfloat16 g_qh[(size_t)NROWS*HD], g_ql[(size_t)NROWS*HD];
__device__ __nv_bfloat16 g_kh[(size_t)NROWS*HD], g_kl[(size_t)NROWS*HD];
__device__ __nv_bfloat16 g_vh[(size_t)NROWS*HD], g_vl[(size_t)NROWS*HD];
__device__ __nv_bfloat16 g_ctxh[(size_t)BATCH*SEQ*DM], g_ctxl[(size_t)BATCH*SEQ*DM];
__device__ __nv_bfloat16 g_woh[(size_t)DM*DM], g_wol[(size_t)DM*DM];
__device__ int g_idx[BATCH*SEQ];
__device__ int g_cnt[BATCH];

// ---------------------------------------------------------------------------
// Packed f32x2 helpers (fp32 qkv projection kernel)
// ---------------------------------------------------------------------------
__device__ __forceinline__ void ffma2(u64 &c, u64 a, u64 b) {
    asm("fma.rn.f32x2 %0, %1, %2, %0;" : "+l"(c) : "l"(a), "l"(b));
}
__device__ __forceinline__ float plo(u64 c) { return __uint_as_float((unsigned)c); }
__device__ __forceinline__ float phi(u64 c) { return __uint_as_float((unsigned)(c >> 32)); }
__device__ __forceinline__ float psum(u64 c) { return plo(c) + phi(c); }

// ---------------------------------------------------------------------------
// fp32 64x64 swizzled tile helpers (qkv projection kernel)
// ---------------------------------------------------------------------------
__device__ __forceinline__ void load_tile_swz(float* __restrict__ dst,
                                              const float* __restrict__ src,
                                              int stride) {
    int t   = threadIdx.x;        // 256 threads
    int seg = t & 15;
    int r   = t >> 4;
#pragma unroll
    for (int p = 0; p < 4; p++, r += 16) {
        float4 v = *(const float4*)(src + (size_t)r * stride + (seg << 2));
        int g = seg ^ ((r >> 2) & 7);
        *(float4*)(dst + r * 64 + (g << 2)) = v;
    }
}

__device__ __forceinline__ void mm_acc_p(const float* __restrict__ As,
                                         const float* __restrict__ Bs,
                                         u64 c2[4][4], int ty, int tx) {
#pragma unroll
    for (int d4 = 0; d4 < 16; d4++) {
        int oa = (ty * 4) * 64 + ((d4 ^ (ty & 7)) << 2);
        int ob = (tx * 4) * 64 + ((d4 ^ (tx & 7)) << 2);
        ulonglong2 a[4], b[4];
#pragma unroll
        for (int i = 0; i < 4; i++) a[i] = *(const ulonglong2*)(As + oa + i * 64);
#pragma unroll
        for (int j = 0; j < 4; j++) b[j] = *(const ulonglong2*)(Bs + ob + j * 64);
#pragma unroll
        for (int i = 0; i < 4; i++)
#pragma unroll
            for (int j = 0; j < 4; j++) {
                ffma2(c2[i][j], a[i].x, b[j].x);
                ffma2(c2[i][j], a[i].y, b[j].y);
            }
    }
}

// ---------------------------------------------------------------------------
// HMMA helpers
// ---------------------------------------------------------------------------
__device__ __forceinline__ u32 s2u(const void* p) {
    return (u32)__cvta_generic_to_shared(p);
}
__device__ __forceinline__ void ldsm4(u32 &r0, u32 &r1, u32 &r2, u32 &r3, u32 a) {
    asm volatile("ldmatrix.sync.aligned.m8n8.x4.shared.b16 {%0,%1,%2,%3}, [%4];"
                 : "=r"(r0), "=r"(r1), "=r"(r2), "=r"(r3) : "r"(a));
}
__device__ __forceinline__ void ldsm2(u32 &r0, u32 &r1, u32 a) {
    asm volatile("ldmatrix.sync.aligned.m8n8.x2.shared.b16 {%0,%1}, [%2];"
                 : "=r"(r0), "=r"(r1) : "r"(a));
}
__device__ __forceinline__ void ldsm2t(u32 &r0, u32 &r1, u32 a) {
    asm volatile("ldmatrix.sync.aligned.m8n8.x2.trans.shared.b16 {%0,%1}, [%2];"
                 : "=r"(r0), "=r"(r1) : "r"(a));
}
__device__ __forceinline__ void mmabf(float c[4], const u32 a[4], u32 b0, u32 b1) {
    asm volatile("mma.sync.aligned.m16n8k16.row.col.f32.bf16.bf16.f32 "
                 "{%0,%1,%2,%3}, {%4,%5,%6,%7}, {%8,%9}, {%0,%1,%2,%3};"
                 : "+f"(c[0]), "+f"(c[1]), "+f"(c[2]), "+f"(c[3])
                 : "r"(a[0]), "r"(a[1]), "r"(a[2]), "r"(a[3]), "r"(b0), "r"(b1));
}
// split (f0,f1) -> packed bf16 hi and lo pairs (f0 in lower half)
__device__ __forceinline__ void split_pair(float f0, float f1, u32 &hi, u32 &lo) {
    __nv_bfloat162 h = __floats2bfloat162_rn(f0, f1);
    float hf0 = __bfloat162float(h.x), hf1 = __bfloat162float(h.y);
    __nv_bfloat162 l = __floats2bfloat162_rn(f0 - hf0, f1 - hf1);
    hi = *reinterpret_cast<u32*>(&h);
    lo = *reinterpret_cast<u32*>(&l);
}

// ---------------------------------------------------------------------------
// bf16 tile fills (swizzled 128B rows: physical seg = seg ^ (row&7))
// 128 threads, 64x64 bf16 tile, source row stride = DM.
// ---------------------------------------------------------------------------
__device__ __forceinline__ void fill_bf16_gather(__nv_bfloat16* __restrict__ dst,
                                                 const __nv_bfloat16* __restrict__ base,
                                                 const int* __restrict__ idxb,
                                                 int k0, int cnt, int t) {
    int seg = t & 7;
    int r   = t >> 3;          // 16 rows per pass
#pragma unroll
    for (int p = 0; p < 4; p++, r += 16) {
        int kr  = k0 + r;
        int row = (kr < cnt) ? idxb[kr] : 0;
        uint4 v = *((const uint4*)(base + (size_t)row * DM) + seg);
        *((uint4*)(dst + r * HD + ((seg ^ (r & 7)) << 3))) = v;
    }
}
__device__ __forceinline__ void fill_bf16_str(__nv_bfloat16* __restrict__ dst,
                                              const __nv_bfloat16* __restrict__ base,
                                              int t) {
    int seg = t & 7;
    int r   = t >> 3;
#pragma unroll
    for (int p = 0; p < 4; p++, r += 16) {
        uint4 v = *((const uint4*)(base + (size_t)r * DM) + seg);
        *((uint4*)(dst + r * HD + ((seg ^ (r & 7)) << 3))) = v;
    }
}

// ---------------------------------------------------------------------------
// Kernel 0: per-batch mask compaction (exact: masked keys softmax to 0.0f).
// ---------------------------------------------------------------------------
__global__ void compact_kernel(const int* __restrict__ mask) {
    __shared__ int cnts[256];
    int b = blockIdx.x;
    int t = threadIdx.x;
    int m[8], c = 0;
#pragma unroll
    for (int e = 0; e < 8; e++) {
        m[e] = mask[b * SEQ + t * 8 + e];
        c += (m[e] != 0);
    }
    cnts[t] = c;
    __syncthreads();
    for (int off = 1; off < 256; off <<= 1) {
        int u = (t >= off) ? cnts[t - off] : 0;
        __syncthreads();
        cnts[t] += u;
        __syncthreads();
    }
    int w = cnts[t] - c;
#pragma unroll
    for (int e = 0; e < 8; e++)
        if (m[e]) g_idx[b * SEQ + (w++)] = t * 8 + e;
    if (t == 255) g_cnt[b] = cnts[255];
}

// ---------------------------------------------------------------------------
// Kernel 0b: Wo permute+split: Woh/Wol[e][h*64+d] = split(Wo[e][d*8+h])
// ---------------------------------------------------------------------------
__global__ void wo_conv_kernel(const float* __restrict__ Wo) {
    int idx = blockIdx.x * 256 + threadIdx.x;   // 0..131071 (pairs)
    int e  = idx >> 8;
    int fp = (idx & 255) << 1;                  // permuted feature, even
    int h = fp >> 6, d = fp & 63;
    float v0 = Wo[(size_t)e * DM + d * 8 + h];
    float v1 = Wo[(size_t)e * DM + (d + 1) * 8 + h];
    u32 hi, lo;
    split_pair(v0, v1, hi, lo);
    *(u32*)(g_woh + (size_t)e * DM + fp) = hi;
    *(u32*)(g_wol + (size_t)e * DM + fp) = lo;
}

// ---------------------------------------------------------------------------
// Kernel 1: per-head QKV projections -> bf16 hi/lo outputs.
// ---------------------------------------------------------------------------
__global__ void qkv_proj_kernel(const float* __restrict__ qin,
                                const float* __restrict__ kin,
                                const float* __restrict__ vin,
                                const float* __restrict__ Wq, const float* __restrict__ bq,
                                const float* __restrict__ Wk, const float* __restrict__ bk,
                                const float* __restrict__ Wv, const float* __restrict__ bv) {
    __shared__ float Xs[4096], Ws[4096];
    const float *in, *W, *bias;
    __nv_bfloat16 *outh, *outl;
    if (blockIdx.y == 0)      { in = qin; W = Wq; bias = bq; outh = g_qh; outl = g_ql; }
    else if (blockIdx.y == 1) { in = kin; W = Wk; bias = bk; outh = g_kh; outl = g_kl; }
    else                      { in = vin; W = Wv; bias = bv; outh = g_vh; outl = g_vl; }

    int r0 = blockIdx.x << 6;
    int t = threadIdx.x, tx = t & 15, ty = t >> 4;

    load_tile_swz(Xs, in + (size_t)r0 * 64, 64);
    load_tile_swz(Ws, W, 64);
    __syncthreads();

    u64 c2[4][4] = {};
    mm_acc_p(Xs, Ws, c2, ty, tx);

#pragma unroll
    for (int i = 0; i < 4; i++) {
        float v0 = psum(c2[i][0]) + bias[tx * 4 + 0];
        float v1 = psum(c2[i][1]) + bias[tx * 4 + 1];
        float v2 = psum(c2[i][2]) + bias[tx * 4 + 2];
        float v3 = psum(c2[i][3]) + bias[tx * 4 + 3];
        u32 h01, l01, h23, l23;
        split_pair(v0, v1, h01, l01);
        split_pair(v2, v3, h23, l23);
        size_t o = (size_t)(r0 + ty * 4 + i) * 64 + tx * 4;
        *(uint2*)(outh + o) = make_uint2(h01, h23);
        *(uint2*)(outl + o) = make_uint2(l01, l23);
    }
}

// ---------------------------------------------------------------------------
// Kernel 2: HMMA flash attention over COMPACTED keys (bf16 hi/lo split).
// 128 threads = 4 warps; warp w owns q-rows [16w, 16w+16).
// Writes ctx as split bf16 in HEAD-MAJOR order: ctx[row][h*64+d].
// ---------------------------------------------------------------------------
__global__ void __launch_bounds__(128) attn_kernel() {
    extern __shared__ __nv_bfloat16 sm[];
    __nv_bfloat16* Kh = sm;
    __nv_bfloat16* Kl = sm + 4096;
    __nv_bfloat16* Vh = sm + 8192;
    __nv_bfloat16* Vl = sm + 12288;

    int bh = blockIdx.y;
    int b = bh >> 3, h = bh & 7;
    int q0 = blockIdx.x << 6;
    int t = threadIdx.x, w = t >> 5, lane = t & 31;

    int cnt = g_cnt[b];
    const int* idxb = g_idx + b * SEQ;

    const __nv_bfloat16* qhb = g_qh + ((size_t)(b * SEQ + q0) * NH + h) * HD;
    const __nv_bfloat16* qlb = g_ql + ((size_t)(b * SEQ + q0) * NH + h) * HD;
    const __nv_bfloat16* khb = g_kh + ((size_t)b * SEQ * NH + h) * HD;
    const __nv_bfloat16* klb = g_kl + ((size_t)b * SEQ * NH + h) * HD;
    const __nv_bfloat16* vhb = g_vh + ((size_t)b * SEQ * NH + h) * HD;
    const __nv_bfloat16* vlb = g_vl + ((size_t)b * SEQ * NH + h) * HD;

    // ---- stage Q (reuse Kh/Kl smem), load A fragments ----
    fill_bf16_str(Kh, qhb, t);
    fill_bf16_str(Kl, qlb, t);
    __syncthreads();

    u32 qh[4][4], ql[4][4];
    {
        int r = (w << 4) + (lane & 7) + (((lane >> 3) & 1) << 3);
#pragma unroll
        for (int ks = 0; ks < 4; ks++) {
            int seg = (ks << 1) + (lane >> 4);
            u32 off = (u32)(r * HD + ((seg ^ (r & 7)) << 3)) * 2;
            ldsm4(qh[ks][0], qh[ks][1], qh[ks][2], qh[ks][3], s2u(Kh) + off);
            ldsm4(ql[ks][0], ql[ks][1], ql[ks][2], ql[ks][3], s2u(Kl) + off);
        }
    }
    __syncthreads();

    float out[8][4] = {};
    float m0 = -3.0e38f, m1 = -3.0e38f, l0 = 0.f, l1 = 0.f;

    int nkt = (cnt + 63) >> 6;
    for (int kt = 0; kt < nkt; kt++) {
        int k0 = kt << 6;
        fill_bf16_gather(Kh, khb, idxb, k0, cnt, t);
        fill_bf16_gather(Kl, klb, idxb, k0, cnt, t);
        fill_bf16_gather(Vh, vhb, idxb, k0, cnt, t);
        fill_bf16_gather(Vl, vlb, idxb, k0, cnt, t);
        __syncthreads();

        // ---- S = Q · K^T (split: hi*hi + hi*lo + lo*hi) ----
        float sacc[8][4] = {};
#pragma unroll
        for (int nb = 0; nb < 8; nb++) {
            int brow = (nb << 3) + (lane & 7);
#pragma unroll
            for (int ks = 0; ks < 4; ks++) {
                int seg = (ks << 1) + ((lane >> 3) & 1);
                u32 off = (u32)(brow * HD + ((seg ^ (brow & 7)) << 3)) * 2;
                u32 bh0, bh1, bl0, bl1;
                ldsm2(bh0, bh1, s2u(Kh) + off);
                ldsm2(bl0, bl1, s2u(Kl) + off);
                mmabf(sacc[nb], qh[ks], bh0, bh1);
                mmabf(sacc[nb], qh[ks], bl0, bl1);
                mmabf(sacc[nb], ql[ks], bh0, bh1);
            }
        }

        // ---- masked-scale + online softmax (2 q-rows per thread) ----
        float mx0 = -3.0e38f, mx1 = -3.0e38f;
#pragma unroll
        for (int nb = 0; nb < 8; nb++)
#pragma unroll
            for (int jj = 0; jj < 2; jj++) {
                int col = k0 + (nb << 3) + ((lane & 3) << 1) + jj;
                bool ok = col < cnt;
                float x0 = ok ? sacc[nb][jj]     * 0.25f : -3.0e38f;
                float x1 = ok ? sacc[nb][2 + jj] * 0.25f : -3.0e38f;
                sacc[nb][jj] = x0;  sacc[nb][2 + jj] = x1;
                mx0 = fmaxf(mx0, x0);  mx1 = fmaxf(mx1, x1);
            }
        mx0 = fmaxf(mx0, __shfl_xor_sync(0xffffffffu, mx0, 1));
        mx0 = fmaxf(mx0, __shfl_xor_sync(0xffffffffu, mx0, 2));
        mx1 = fmaxf(mx1, __shfl_xor_sync(0xffffffffu, mx1, 1));
        mx1 = fmaxf(mx1, __shfl_xor_sync(0xffffffffu, mx1, 2));
        float mn0 = fmaxf(m0, mx0), mn1 = fmaxf(m1, mx1);
        float a0 = __expf(m0 - mn0), a1 = __expf(m1 - mn1);
        float rs0 = 0.f, rs1 = 0.f;
#pragma unroll
        for (int nb = 0; nb < 8; nb++)
#pragma unroll
            for (int jj = 0; jj < 2; jj++) {
                float p0 = __expf(sacc[nb][jj]     - mn0);
                float p1 = __expf(sacc[nb][2 + jj] - mn1);
                sacc[nb][jj] = p0;  sacc[nb][2 + jj] = p1;
                rs0 += p0;  rs1 += p1;
            }
        rs0 += __shfl_xor_sync(0xffffffffu, rs0, 1);
        rs0 += __shfl_xor_sync(0xffffffffu, rs0, 2);
        rs1 += __shfl_xor_sync(0xffffffffu, rs1, 1);
        rs1 += __shfl_xor_sync(0xffffffffu, rs1, 2);
        l0 = l0 * a0 + rs0;  l1 = l1 * a1 + rs1;
        m0 = mn0;  m1 = mn1;
#pragma unroll
        for (int nbd = 0; nbd < 8; nbd++) {
            out[nbd][0] *= a0;  out[nbd][1] *= a0;
            out[nbd][2] *= a1;  out[nbd][3] *= a1;
        }

        // ---- repack P (C-frag) into A-frags, bf16 hi/lo ----
        u32 ph[4][4], pl[4][4];
#pragma unroll
        for (int e = 0; e < 4; e++) {
            int n0 = 2 * e, n1 = 2 * e + 1;
            split_pair(sacc[n0][0], sacc[n0][1], ph[e][0], pl[e][0]);
            split_pair(sacc[n0][2], sacc[n0][3], ph[e][1], pl[e][1]);
            split_pair(sacc[n1][0], sacc[n1][1], ph[e][2], pl[e][2]);
            split_pair(sacc[n1][2], sacc[n1][3], ph[e][3], pl[e][3]);
        }

        // ---- O += P · V (V^T via ldmatrix.trans; split products) ----
#pragma unroll
        for (int nbd = 0; nbd < 8; nbd++) {
#pragma unroll
            for (int e = 0; e < 4; e++) {
                int vrow = (e << 4) + (lane & 15);
                u32 off = (u32)(vrow * HD + ((nbd ^ (vrow & 7)) << 3)) * 2;
                u32 vh0, vh1, vl0, vl1;
                ldsm2t(vh0, vh1, s2u(Vh) + off);
                ldsm2t(vl0, vl1, s2u(Vl) + off);
                mmabf(out[nbd], ph[e], vh0, vh1);
                mmabf(out[nbd], ph[e], vl0, vl1);
                mmabf(out[nbd], pl[e], vh0, vh1);
            }
        }
        __syncthreads();
    }

    // ---- epilogue: ctx as split bf16, head-major [row][h*64+d] ----
    float inv0 = 1.0f / l0, inv1 = 1.0f / l1;
    int row0 = q0 + (w << 4) + (lane >> 2);
    size_t base0 = ((size_t)b * SEQ + row0) * DM + h * HD;
    size_t base1 = base0 + (size_t)8 * DM;
#pragma unroll
    for (int nbd = 0; nbd < 8; nbd++) {
        int d = (nbd << 3) + ((lane & 3) << 1);
        u32 hi, lo;
        split_pair(out[nbd][0] * inv0, out[nbd][1] * inv0, hi, lo);
        *(u32*)(g_ctxh + base0 + d) = hi;
        *(u32*)(g_ctxl + base0 + d) = lo;
        split_pair(out[nbd][2] * inv1, out[nbd][3] * inv1, hi, lo);
        *(u32*)(g_ctxh + base1 + d) = hi;
        *(u32*)(g_ctxl + base1 + d) = lo;
    }
}

// ---------------------------------------------------------------------------
// Kernel 3: output projection (HMMA split-bf16).
// ctx[4096x512] (head-major features) @ Wop[512x512]^T + bo.
// 128 threads = 4 warps, tile M=64 N=64, K=512 in 8 chunks.
// ---------------------------------------------------------------------------
__global__ void __launch_bounds__(128) out_proj_kernel(const float* __restrict__ bo,
                                                       float* __restrict__ y) {
    __shared__ __nv_bfloat16 Xh[4096], Xl[4096], Wh[4096], Wl[4096];
    int r0 = blockIdx.x << 6;
    int e0 = blockIdx.y << 6;
    int t = threadIdx.x, w = t >> 5, lane = t & 31;

    float out[8][4] = {};

    for (int kt = 0; kt < DM / 64; kt++) {
        fill_bf16_str(Xh, g_ctxh + (size_t)r0 * DM + kt * 64, t);
        fill_bf16_str(Xl, g_ctxl + (size_t)r0 * DM + kt * 64, t);
        fill_bf16_str(Wh, g_woh + (size_t)e0 * DM + kt * 64, t);
        fill_bf16_str(Wl, g_wol + (size_t)e0 * DM + kt * 64, t);
        __syncthreads();

        u32 ah[4][4], al[4][4];
        {
            int r = (w << 4) + (lane & 7) + (((lane >> 3) & 1) << 3);
#pragma unroll
            for (int ks = 0; ks < 4; ks++) {
                int seg = (ks << 1) + (lane >> 4);
                u32 off = (u32)(r * HD + ((seg ^ (r & 7)) << 3)) * 2;
                ldsm4(ah[ks][0], ah[ks][1], ah[ks][2], ah[ks][3], s2u(Xh) + off);
                ldsm4(al[ks][0], al[ks][1], al[ks][2], al[ks][3], s2u(Xl) + off);
            }
        }

#pragma unroll
        for (int nb = 0; nb < 8; nb++) {
            int brow = (nb << 3) + (lane & 7);
#pragma unroll
            for (int ks = 0; ks < 4; ks++) {
                int seg = (ks << 1) + ((lane >> 3) & 1);
                u32 off = (u32)(brow * HD + ((seg ^ (brow & 7)) << 3)) * 2;
                u32 bh0, bh1, bl0, bl1;
                ldsm2(bh0, bh1, s2u(Wh) + off);
                ldsm2(bl0, bl1, s2u(Wl) + off);
                mmabf(out[nb], ah[ks], bh0, bh1);
                mmabf(out[nb], ah[ks], bl0, bl1);
                mmabf(out[nb], al[ks], bh0, bh1);
            }
        }
        __syncthreads();
    }

    // epilogue: bias + fp32 writes (8B pairs)
    int row0 = r0 + (w << 4) + (lane >> 2);
#pragma unroll
    for (int nb = 0; nb < 8; nb++) {
        int e = e0 + (nb << 3) + ((lane & 3) << 1);
        float b0 = bo[e], b1 = bo[e + 1];
        *(float2*)(y + (size_t)row0 * DM + e) =
            make_float2(out[nb][0] + b0, out[nb][1] + b1);
        *(float2*)(y + (size_t)(row0 + 8) * DM + e) =
            make_float2(out[nb][2] + b0, out[nb][3] + b1);
    }
}

// ---------------------------------------------------------------------------
extern "C" void kernel_launch(void* const* d_in, const int* in_sizes, int n_in,
                              void* d_out, int out_size) {
    const float* query = (const float*)d_in[0];
    const float* key   = (const float*)d_in[1];
    const float* value = (const float*)d_in[2];
    const float* Wq    = (const float*)d_in[3];
    const float* bq    = (const float*)d_in[4];
    const float* Wk    = (const float*)d_in[5];
    const float* bk    = (const float*)d_in[6];
    const float* Wv    = (const float*)d_in[7];
    const float* bv    = (const float*)d_in[8];
    const float* Wo    = (const float*)d_in[9];
    const float* bo    = (const float*)d_in[10];
    const int*   mask  = (const int*)d_in[11];

    cudaFuncSetAttribute(attn_kernel, cudaFuncAttributeMaxDynamicSharedMemorySize,
                         48 * 1024);

    compact_kernel<<<BATCH, 256>>>(mask);
    wo_conv_kernel<<<512, 256>>>(Wo);
    qkv_proj_kernel<<<dim3(NROWS / 64, 3), 256>>>(query, key, value,
                                                  Wq, bq, Wk, bk, Wv, bv);
    attn_kernel<<<dim3(SEQ / 64, BATCH * NH), 128, 32 * 1024>>>();
    out_proj_kernel<<<dim3(BATCH * SEQ / 64, DM / 64), 128>>>(bo, (float*)d_out);
}

// round 7
// speedup vs baseline: 5.2834x; 1.2643x over previous
#include <cuda_runtime.h>
#include <cuda_bf16.h>
#include <math.h>
#include <stdint.h>

#define BATCH 2
#define SEQ   2048
#define NH    8
#define HD    64
#define DM    512
#define NROWS (BATCH*SEQ*NH)

typedef unsigned long long u64;
typedef unsigned int u32;

// Scratch (static __device__ — no allocation anywhere)
__device__ __nv_bfloat16 g_qh[(size_t)NROWS*HD], g_ql[(size_t)NROWS*HD];
__device__ __nv_bfloat16 g_kh[(size_t)NROWS*HD];
__device__ __nv_bfloat16 g_vh[(size_t)NROWS*HD], g_vl[(size_t)NROWS*HD];
__device__ __nv_bfloat16 g_ctxh[(size_t)BATCH*SEQ*DM], g_ctxl[(size_t)BATCH*SEQ*DM];
__device__ __nv_bfloat16 g_woh[(size_t)DM*DM], g_wol[(size_t)DM*DM];
__device__ int g_idx[BATCH*SEQ];
__device__ int g_cnt[BATCH];

// ---------------------------------------------------------------------------
// Packed f32x2 helpers (fp32 qkv projection kernel)
// ---------------------------------------------------------------------------
__device__ __forceinline__ void ffma2(u64 &c, u64 a, u64 b) {
    asm("fma.rn.f32x2 %0, %1, %2, %0;" : "+l"(c) : "l"(a), "l"(b));
}
__device__ __forceinline__ float plo(u64 c) { return __uint_as_float((unsigned)c); }
__device__ __forceinline__ float phi(u64 c) { return __uint_as_float((unsigned)(c >> 32)); }
__device__ __forceinline__ float psum(u64 c) { return plo(c) + phi(c); }

// ---------------------------------------------------------------------------
// fp32 64x64 swizzled tile helpers (qkv projection kernel)
// ---------------------------------------------------------------------------
__device__ __forceinline__ void load_tile_swz(float* __restrict__ dst,
                                              const float* __restrict__ src,
                                              int stride) {
    int t   = threadIdx.x;        // 256 threads
    int seg = t & 15;
    int r   = t >> 4;
#pragma unroll
    for (int p = 0; p < 4; p++, r += 16) {
        float4 v = *(const float4*)(src + (size_t)r * stride + (seg << 2));
        int g = seg ^ ((r >> 2) & 7);
        *(float4*)(dst + r * 64 + (g << 2)) = v;
    }
}

__device__ __forceinline__ void mm_acc_p(const float* __restrict__ As,
                                         const float* __restrict__ Bs,
                                         u64 c2[4][4], int ty, int tx) {
#pragma unroll
    for (int d4 = 0; d4 < 16; d4++) {
        int oa = (ty * 4) * 64 + ((d4 ^ (ty & 7)) << 2);
        int ob = (tx * 4) * 64 + ((d4 ^ (tx & 7)) << 2);
        ulonglong2 a[4], b[4];
#pragma unroll
        for (int i = 0; i < 4; i++) a[i] = *(const ulonglong2*)(As + oa + i * 64);
#pragma unroll
        for (int j = 0; j < 4; j++) b[j] = *(const ulonglong2*)(Bs + ob + j * 64);
#pragma unroll
        for (int i = 0; i < 4; i++)
#pragma unroll
            for (int j = 0; j < 4; j++) {
                ffma2(c2[i][j], a[i].x, b[j].x);
                ffma2(c2[i][j], a[i].y, b[j].y);
            }
    }
}

// ---------------------------------------------------------------------------
// HMMA + async-copy helpers
// ---------------------------------------------------------------------------
__device__ __forceinline__ u32 s2u(const void* p) {
    return (u32)__cvta_generic_to_shared(p);
}
__device__ __forceinline__ void ldsm4(u32 &r0, u32 &r1, u32 &r2, u32 &r3, u32 a) {
    asm volatile("ldmatrix.sync.aligned.m8n8.x4.shared.b16 {%0,%1,%2,%3}, [%4];"
                 : "=r"(r0), "=r"(r1), "=r"(r2), "=r"(r3) : "r"(a));
}
__device__ __forceinline__ void ldsm2(u32 &r0, u32 &r1, u32 a) {
    asm volatile("ldmatrix.sync.aligned.m8n8.x2.shared.b16 {%0,%1}, [%2];"
                 : "=r"(r0), "=r"(r1) : "r"(a));
}
__device__ __forceinline__ void ldsm2t(u32 &r0, u32 &r1, u32 a) {
    asm volatile("ldmatrix.sync.aligned.m8n8.x2.trans.shared.b16 {%0,%1}, [%2];"
                 : "=r"(r0), "=r"(r1) : "r"(a));
}
__device__ __forceinline__ void mmabf(float c[4], const u32 a[4], u32 b0, u32 b1) {
    asm volatile("mma.sync.aligned.m16n8k16.row.col.f32.bf16.bf16.f32 "
                 "{%0,%1,%2,%3}, {%4,%5,%6,%7}, {%8,%9}, {%0,%1,%2,%3};"
                 : "+f"(c[0]), "+f"(c[1]), "+f"(c[2]), "+f"(c[3])
                 : "r"(a[0]), "r"(a[1]), "r"(a[2]), "r"(a[3]), "r"(b0), "r"(b1));
}
__device__ __forceinline__ void cp16(u32 dst, const void* src) {
    asm volatile("cp.async.cg.shared.global [%0], [%1], 16;" :: "r"(dst), "l"(src));
}
__device__ __forceinline__ void cp_commit() {
    asm volatile("cp.async.commit_group;");
}
template<int N> __device__ __forceinline__ void cp_wait() {
    asm volatile("cp.async.wait_group %0;" :: "n"(N));
}
// split (f0,f1) -> packed bf16 hi and lo pairs (f0 in lower half)
__device__ __forceinline__ void split_pair(float f0, float f1, u32 &hi, u32 &lo) {
    __nv_bfloat162 h = __floats2bfloat162_rn(f0, f1);
    float hf0 = __bfloat162float(h.x), hf1 = __bfloat162float(h.y);
    __nv_bfloat162 l = __floats2bfloat162_rn(f0 - hf0, f1 - hf1);
    hi = *reinterpret_cast<u32*>(&h);
    lo = *reinterpret_cast<u32*>(&l);
}

// ---------------------------------------------------------------------------
// bf16 tile fill (swizzled 128B rows: physical seg = seg ^ (row&7))
// 128 threads, 64x64 bf16 tile, source row stride = DM.
// ---------------------------------------------------------------------------
__device__ __forceinline__ void fill_bf16_str(__nv_bfloat16* __restrict__ dst,
                                              const __nv_bfloat16* __restrict__ base,
                                              int t) {
    int seg = t & 7;
    int r   = t >> 3;
#pragma unroll
    for (int p = 0; p < 4; p++, r += 16) {
        uint4 v = *((const uint4*)(base + (size_t)r * DM) + seg);
        *((uint4*)(dst + r * HD + ((seg ^ (r & 7)) << 3))) = v;
    }
}

// ---------------------------------------------------------------------------
// Kernel 0: per-batch mask compaction (exact: masked keys softmax to 0.0f).
// ---------------------------------------------------------------------------
__global__ void compact_kernel(const int* __restrict__ mask) {
    __shared__ int cnts[256];
    int b = blockIdx.x;
    int t = threadIdx.x;
    int m[8], c = 0;
#pragma unroll
    for (int e = 0; e < 8; e++) {
        m[e] = mask[b * SEQ + t * 8 + e];
        c += (m[e] != 0);
    }
    cnts[t] = c;
    __syncthreads();
    for (int off = 1; off < 256; off <<= 1) {
        int u = (t >= off) ? cnts[t - off] : 0;
        __syncthreads();
        cnts[t] += u;
        __syncthreads();
    }
    int w = cnts[t] - c;
#pragma unroll
    for (int e = 0; e < 8; e++)
        if (m[e]) g_idx[b * SEQ + (w++)] = t * 8 + e;
    if (t == 255) g_cnt[b] = cnts[255];
}

// ---------------------------------------------------------------------------
// Kernel 0b: Wo permute+split: Woh/Wol[e][h*64+d] = split(Wo[e][d*8+h])
// ---------------------------------------------------------------------------
__global__ void wo_conv_kernel(const float* __restrict__ Wo) {
    int idx = blockIdx.x * 256 + threadIdx.x;   // 0..131071 (pairs)
    int e  = idx >> 8;
    int fp = (idx & 255) << 1;                  // permuted feature, even
    int h = fp >> 6, d = fp & 63;
    float v0 = Wo[(size_t)e * DM + d * 8 + h];
    float v1 = Wo[(size_t)e * DM + (d + 1) * 8 + h];
    u32 hi, lo;
    split_pair(v0, v1, hi, lo);
    *(u32*)(g_woh + (size_t)e * DM + fp) = hi;
    *(u32*)(g_wol + (size_t)e * DM + fp) = lo;
}

// ---------------------------------------------------------------------------
// Kernel 1: per-head QKV projections -> bf16 hi/lo outputs (K: hi only).
// ---------------------------------------------------------------------------
__global__ void qkv_proj_kernel(const float* __restrict__ qin,
                                const float* __restrict__ kin,
                                const float* __restrict__ vin,
                                const float* __restrict__ Wq, const float* __restrict__ bq,
                                const float* __restrict__ Wk, const float* __restrict__ bk,
                                const float* __restrict__ Wv, const float* __restrict__ bv) {
    __shared__ float Xs[4096], Ws[4096];
    const float *in, *W, *bias;
    __nv_bfloat16 *outh, *outl;
    bool wlo = true;
    if (blockIdx.y == 0)      { in = qin; W = Wq; bias = bq; outh = g_qh; outl = g_ql; }
    else if (blockIdx.y == 1) { in = kin; W = Wk; bias = bk; outh = g_kh; outl = g_qh; wlo = false; }
    else                      { in = vin; W = Wv; bias = bv; outh = g_vh; outl = g_vl; }

    int r0 = blockIdx.x << 6;
    int t = threadIdx.x, tx = t & 15, ty = t >> 4;

    load_tile_swz(Xs, in + (size_t)r0 * 64, 64);
    load_tile_swz(Ws, W, 64);
    __syncthreads();

    u64 c2[4][4] = {};
    mm_acc_p(Xs, Ws, c2, ty, tx);

#pragma unroll
    for (int i = 0; i < 4; i++) {
        float v0 = psum(c2[i][0]) + bias[tx * 4 + 0];
        float v1 = psum(c2[i][1]) + bias[tx * 4 + 1];
        float v2 = psum(c2[i][2]) + bias[tx * 4 + 2];
        float v3 = psum(c2[i][3]) + bias[tx * 4 + 3];
        u32 h01, l01, h23, l23;
        split_pair(v0, v1, h01, l01);
        split_pair(v2, v3, h23, l23);
        size_t o = (size_t)(r0 + ty * 4 + i) * 64 + tx * 4;
        *(uint2*)(outh + o) = make_uint2(h01, h23);
        if (wlo) *(uint2*)(outl + o) = make_uint2(l01, l23);
    }
}

// ---------------------------------------------------------------------------
// Kernel 2: HMMA flash attention, 2-stage cp.async pipeline, compacted keys.
// 128 threads = 4 warps; warp w owns q-rows [16w, 16w+16).
// smem: stage s at sm + s*12288 {Kh, Vh, Vl}, then idx[2048].
// ---------------------------------------------------------------------------
__global__ void __launch_bounds__(128, 3) attn_kernel() {
    extern __shared__ __nv_bfloat16 sm[];
    int* sidx = (int*)(sm + 24576);

    int bh = blockIdx.y;
    int b = bh >> 3, h = bh & 7;
    int q0 = blockIdx.x << 6;
    int t = threadIdx.x, w = t >> 5, lane = t & 31;

    int cnt = g_cnt[b];
    int nkt = (cnt + 63) >> 6;
    const int* idxb = g_idx + b * SEQ;

    const __nv_bfloat16* qhb = g_qh + ((size_t)(b * SEQ + q0) * NH + h) * HD;
    const __nv_bfloat16* qlb = g_ql + ((size_t)(b * SEQ + q0) * NH + h) * HD;
    const __nv_bfloat16* khb = g_kh + ((size_t)b * SEQ * NH + h) * HD;
    const __nv_bfloat16* vhb = g_vh + ((size_t)b * SEQ * NH + h) * HD;
    const __nv_bfloat16* vlb = g_vl + ((size_t)b * SEQ * NH + h) * HD;

    // ---- stage Q into stage-0 buffers, prefetch index list ----
    fill_bf16_str(sm, qhb, t);
    fill_bf16_str(sm + 4096, qlb, t);
    {
        int padded = nkt << 6;
        for (int i = t; i < padded; i += 128) sidx[i] = (i < cnt) ? idxb[i] : 0;
    }
    __syncthreads();

    u32 qh[4][4], ql[4][4];
    {
        int r = (w << 4) + (lane & 7) + (((lane >> 3) & 1) << 3);
#pragma unroll
        for (int ks = 0; ks < 4; ks++) {
            int seg = (ks << 1) + (lane >> 4);
            u32 off = (u32)(r * HD + ((seg ^ (r & 7)) << 3)) * 2;
            ldsm4(qh[ks][0], qh[ks][1], qh[ks][2], qh[ks][3], s2u(sm) + off);
            ldsm4(ql[ks][0], ql[ks][1], ql[ks][2], ql[ks][3], s2u(sm + 4096) + off);
        }
    }
    __syncthreads();   // all warps done reading Q staging before cp.async overwrites

    // ---- pipeline prologue ----
    u32 smb = s2u(sm);
    int fseg = t & 7, frow = t >> 3;
#define PIPE_FILL(stage, k0)                                                      \
    {                                                                             \
        int r_ = frow;                                                            \
        u32 sb_ = smb + (stage) * 24576;                                          \
        _Pragma("unroll")                                                         \
        for (int p_ = 0; p_ < 4; p_++, r_ += 16) {                                \
            int row_ = sidx[(k0) + r_];                                           \
            size_t go_ = (size_t)row_ * DM + (fseg << 3);                         \
            u32 do_ = (u32)(r_ * HD + ((fseg ^ (r_ & 7)) << 3)) * 2;              \
            cp16(sb_ + do_,         khb + go_);                                   \
            cp16(sb_ + 8192 + do_,  vhb + go_);                                   \
            cp16(sb_ + 16384 + do_, vlb + go_);                                   \
        }                                                                         \
        cp_commit();                                                              \
    }

    PIPE_FILL(0, 0);
    if (nkt > 1) PIPE_FILL(1, 64);

    float out[8][4] = {};
    float m0 = -3.0e38f, m1 = -3.0e38f, l0 = 0.f, l1 = 0.f;

    for (int kt = 0; kt < nkt; kt++) {
        if (kt + 1 < nkt) cp_wait<1>(); else cp_wait<0>();
        __syncthreads();

        const __nv_bfloat16* Kh = sm + (kt & 1) * 12288;
        const __nv_bfloat16* Vh = Kh + 4096;
        const __nv_bfloat16* Vl = Kh + 8192;
        int k0 = kt << 6;

        // ---- S = Q · K^T (Q split hi/lo, K bf16) ----
        float sacc[8][4] = {};
#pragma unroll
        for (int nb = 0; nb < 8; nb++) {
            int brow = (nb << 3) + (lane & 7);
#pragma unroll
            for (int ks = 0; ks < 4; ks++) {
                int seg = (ks << 1) + ((lane >> 3) & 1);
                u32 off = (u32)(brow * HD + ((seg ^ (brow & 7)) << 3)) * 2;
                u32 bh0, bh1;
                ldsm2(bh0, bh1, s2u(Kh) + off);
                mmabf(sacc[nb], qh[ks], bh0, bh1);
                mmabf(sacc[nb], ql[ks], bh0, bh1);
            }
        }

        // ---- masked-scale + online softmax (2 q-rows per thread) ----
        float mx0 = -3.0e38f, mx1 = -3.0e38f;
#pragma unroll
        for (int nb = 0; nb < 8; nb++)
#pragma unroll
            for (int jj = 0; jj < 2; jj++) {
                int col = k0 + (nb << 3) + ((lane & 3) << 1) + jj;
                bool ok = col < cnt;
                float x0 = ok ? sacc[nb][jj]     * 0.25f : -3.0e38f;
                float x1 = ok ? sacc[nb][2 + jj] * 0.25f : -3.0e38f;
                sacc[nb][jj] = x0;  sacc[nb][2 + jj] = x1;
                mx0 = fmaxf(mx0, x0);  mx1 = fmaxf(mx1, x1);
            }
        mx0 = fmaxf(mx0, __shfl_xor_sync(0xffffffffu, mx0, 1));
        mx0 = fmaxf(mx0, __shfl_xor_sync(0xffffffffu, mx0, 2));
        mx1 = fmaxf(mx1, __shfl_xor_sync(0xffffffffu, mx1, 1));
        mx1 = fmaxf(mx1, __shfl_xor_sync(0xffffffffu, mx1, 2));
        float mn0 = fmaxf(m0, mx0), mn1 = fmaxf(m1, mx1);
        float a0 = __expf(m0 - mn0), a1 = __expf(m1 - mn1);
        float rs0 = 0.f, rs1 = 0.f;
#pragma unroll
        for (int nb = 0; nb < 8; nb++)
#pragma unroll
            for (int jj = 0; jj < 2; jj++) {
                float p0 = __expf(sacc[nb][jj]     - mn0);
                float p1 = __expf(sacc[nb][2 + jj] - mn1);
                sacc[nb][jj] = p0;  sacc[nb][2 + jj] = p1;
                rs0 += p0;  rs1 += p1;
            }
        rs0 += __shfl_xor_sync(0xffffffffu, rs0, 1);
        rs0 += __shfl_xor_sync(0xffffffffu, rs0, 2);
        rs1 += __shfl_xor_sync(0xffffffffu, rs1, 1);
        rs1 += __shfl_xor_sync(0xffffffffu, rs1, 2);
        l0 = l0 * a0 + rs0;  l1 = l1 * a1 + rs1;
        m0 = mn0;  m1 = mn1;
#pragma unroll
        for (int nbd = 0; nbd < 8; nbd++) {
            out[nbd][0] *= a0;  out[nbd][1] *= a0;
            out[nbd][2] *= a1;  out[nbd][3] *= a1;
        }

        // ---- repack P (C-frag) into A-frags, bf16 hi/lo ----
        u32 ph[4][4], pl[4][4];
#pragma unroll
        for (int e = 0; e < 4; e++) {
            int n0 = 2 * e, n1 = 2 * e + 1;
            split_pair(sacc[n0][0], sacc[n0][1], ph[e][0], pl[e][0]);
            split_pair(sacc[n0][2], sacc[n0][3], ph[e][1], pl[e][1]);
            split_pair(sacc[n1][0], sacc[n1][1], ph[e][2], pl[e][2]);
            split_pair(sacc[n1][2], sacc[n1][3], ph[e][3], pl[e][3]);
        }

        // ---- O += P · V (V^T via ldmatrix.trans; split products) ----
#pragma unroll
        for (int nbd = 0; nbd < 8; nbd++) {
#pragma unroll
            for (int e = 0; e < 4; e++) {
                int vrow = (e << 4) + (lane & 15);
                u32 off = (u32)(vrow * HD + ((nbd ^ (vrow & 7)) << 3)) * 2;
                u32 vh0, vh1, vl0, vl1;
                ldsm2t(vh0, vh1, s2u(Vh) + off);
                ldsm2t(vl0, vl1, s2u(Vl) + off);
                mmabf(out[nbd], ph[e], vh0, vh1);
                mmabf(out[nbd], ph[e], vl0, vl1);
                mmabf(out[nbd], pl[e], vh0, vh1);
            }
        }
        __syncthreads();                       // buffer kt%2 free for refill
        if (kt + 2 < nkt) PIPE_FILL(kt & 1, (kt + 2) << 6);
    }

    // ---- epilogue: ctx as split bf16, head-major [row][h*64+d] ----
    float inv0 = 1.0f / l0, inv1 = 1.0f / l1;
    int row0 = q0 + (w << 4) + (lane >> 2);
    size_t base0 = ((size_t)b * SEQ + row0) * DM + h * HD;
    size_t base1 = base0 + (size_t)8 * DM;
#pragma unroll
    for (int nbd = 0; nbd < 8; nbd++) {
        int d = (nbd << 3) + ((lane & 3) << 1);
        u32 hi, lo;
        split_pair(out[nbd][0] * inv0, out[nbd][1] * inv0, hi, lo);
        *(u32*)(g_ctxh + base0 + d) = hi;
        *(u32*)(g_ctxl + base0 + d) = lo;
        split_pair(out[nbd][2] * inv1, out[nbd][3] * inv1, hi, lo);
        *(u32*)(g_ctxh + base1 + d) = hi;
        *(u32*)(g_ctxl + base1 + d) = lo;
    }
}

// ---------------------------------------------------------------------------
// Kernel 3: output projection (HMMA split-bf16).
// ctx[4096x512] (head-major features) @ Wop[512x512]^T + bo.
// ---------------------------------------------------------------------------
__global__ void __launch_bounds__(128) out_proj_kernel(const float* __restrict__ bo,
                                                       float* __restrict__ y) {
    __shared__ __nv_bfloat16 Xh[4096], Xl[4096], Wh[4096], Wl[4096];
    int r0 = blockIdx.x << 6;
    int e0 = blockIdx.y << 6;
    int t = threadIdx.x, w = t >> 5, lane = t & 31;

    float out[8][4] = {};

    for (int kt = 0; kt < DM / 64; kt++) {
        fill_bf16_str(Xh, g_ctxh + (size_t)r0 * DM + kt * 64, t);
        fill_bf16_str(Xl, g_ctxl + (size_t)r0 * DM + kt * 64, t);
        fill_bf16_str(Wh, g_woh + (size_t)e0 * DM + kt * 64, t);
        fill_bf16_str(Wl, g_wol + (size_t)e0 * DM + kt * 64, t);
        __syncthreads();

        u32 ah[4][4], al[4][4];
        {
            int r = (w << 4) + (lane & 7) + (((lane >> 3) & 1) << 3);
#pragma unroll
            for (int ks = 0; ks < 4; ks++) {
                int seg = (ks << 1) + (lane >> 4);
                u32 off = (u32)(r * HD + ((seg ^ (r & 7)) << 3)) * 2;
                ldsm4(ah[ks][0], ah[ks][1], ah[ks][2], ah[ks][3], s2u(Xh) + off);
                ldsm4(al[ks][0], al[ks][1], al[ks][2], al[ks][3], s2u(Xl) + off);
            }
        }

#pragma unroll
        for (int nb = 0; nb < 8; nb++) {
            int brow = (nb << 3) + (lane & 7);
#pragma unroll
            for (int ks = 0; ks < 4; ks++) {
                int seg = (ks << 1) + ((lane >> 3) & 1);
                u32 off = (u32)(brow * HD + ((seg ^ (brow & 7)) << 3)) * 2;
                u32 bh0, bh1, bl0, bl1;
                ldsm2(bh0, bh1, s2u(Wh) + off);
                ldsm2(bl0, bl1, s2u(Wl) + off);
                mmabf(out[nb], ah[ks], bh0, bh1);
                mmabf(out[nb], ah[ks], bl0, bl1);
                mmabf(out[nb], al[ks], bh0, bh1);
            }
        }
        __syncthreads();
    }

    // epilogue: bias + fp32 writes (8B pairs)
    int row0 = r0 + (w << 4) + (lane >> 2);
#pragma unroll
    for (int nb = 0; nb < 8; nb++) {
        int e = e0 + (nb << 3) + ((lane & 3) << 1);
        float b0 = bo[e], b1 = bo[e + 1];
        *(float2*)(y + (size_t)row0 * DM + e) =
            make_float2(out[nb][0] + b0, out[nb][1] + b1);
        *(float2*)(y + (size_t)(row0 + 8) * DM + e) =
            make_float2(out[nb][2] + b0, out[nb][3] + b1);
    }
}

// ---------------------------------------------------------------------------
extern "C" void kernel_launch(void* const* d_in, const int* in_sizes, int n_in,
                              void* d_out, int out_size) {
    const float* query = (const float*)d_in[0];
    const float* key   = (const float*)d_in[1];
    const float* value = (const float*)d_in[2];
    const float* Wq    = (const float*)d_in[3];
    const float* bq    = (const float*)d_in[4];
    const float* Wk    = (const float*)d_in[5];
    const float* bk    = (const float*)d_in[6];
    const float* Wv    = (const float*)d_in[7];
    const float* bv    = (const float*)d_in[8];
    const float* Wo    = (const float*)d_in[9];
    const float* bo    = (const float*)d_in[10];
    const int*   mask  = (const int*)d_in[11];

    // smem: 2 stages * 24KB + 8KB idx = 56KB
    cudaFuncSetAttribute(attn_kernel, cudaFuncAttributeMaxDynamicSharedMemorySize,
                         57344);

    compact_kernel<<<BATCH, 256>>>(mask);
    wo_conv_kernel<<<512, 256>>>(Wo);
    qkv_proj_kernel<<<dim3(NROWS / 64, 3), 256>>>(query, key, value,
                                                  Wq, bq, Wk, bk, Wv, bv);
    attn_kernel<<<dim3(SEQ / 64, BATCH * NH), 128, 57344>>>();
    out_proj_kernel<<<dim3(BATCH * SEQ / 64, DM / 64), 128>>>(bo, (float*)d_out);
}